// round 3
// baseline (speedup 1.0000x reference)
#include <cuda_runtime.h>
#include <cuda_bf16.h>
#include <cstddef>

// Problem constants (registry shape): E=8, H=1024, I=2816, T=8192.
// T and E are derived from in_sizes at launch for robustness; H/I fixed.
#define HID 1024
#define INTER 2816
#define MAX_T 8192

// Scratch: o1/inter and o2. 92.3 MB each, static device globals (allowed).
__device__ float g_buf1[(size_t)MAX_T * INTER];
__device__ float g_buf2[(size_t)MAX_T * INTER];

// ---------------------------------------------------------------------------
// Grouped SGEMM: C[start+m0 .. ] = A[seg] * W[e], W[e] is K x N row-major.
// Block tile 128x128, BK=8, 256 threads, 8x8 per-thread microtile.
// grid = (ceil(T/128), N/128, E); blocks beyond the expert's segment exit.
// ---------------------------------------------------------------------------
#define BM 128
#define BN 128
#define BK 8
#define TM 8
#define TN 8

__global__ __launch_bounds__(256, 2)
void grouped_gemm_kernel(const float* __restrict__ A,
                         const float* __restrict__ W,
                         float* __restrict__ C,
                         const int* __restrict__ tokens_per_expert,
                         int K, int N)
{
    const int e = blockIdx.z;

    // Segment start for expert e (E is tiny; 8 cached loads).
    int start = 0;
    #pragma unroll 1
    for (int i = 0; i < e; ++i) start += tokens_per_expert[i];
    const int cnt = tokens_per_expert[e];

    const int m0 = blockIdx.x * BM;
    if (m0 >= cnt) return;                 // empty tile for this expert
    const int rows = min(BM, cnt - m0);

    const float* Ae = A + (size_t)(start + m0) * K;
    const float* We = W + (size_t)e * K * N;
    float*       Ce = C + (size_t)(start + m0) * N;
    const int n0 = blockIdx.y * BN;        // N is a multiple of BN here

    __shared__ float As[BK][BM];           // A stored transposed
    __shared__ float Bs[BK][BN];

    const int tid  = threadIdx.x;          // 0..255
    const int tcol = tid % (BN / TN);      // 0..15
    const int trow = tid / (BN / TN);      // 0..15

    float acc[TM][TN];
    #pragma unroll
    for (int i = 0; i < TM; ++i)
        #pragma unroll
        for (int j = 0; j < TN; ++j) acc[i][j] = 0.f;

    float ra[TM], rb[TN];

    for (int k0 = 0; k0 < K; k0 += BK) {
        // Load A tile: BM x BK (1024 elems, 4 per thread)
        #pragma unroll
        for (int i = 0; i < (BM * BK) / 256; ++i) {
            int idx = tid + i * 256;
            int r = idx / BK;
            int c = idx % BK;
            float v = (r < rows) ? Ae[(size_t)r * K + (k0 + c)] : 0.f;
            As[c][r] = v;
        }
        // Load B tile: BK x BN (1024 elems, 4 per thread), coalesced on N
        #pragma unroll
        for (int i = 0; i < (BK * BN) / 256; ++i) {
            int idx = tid + i * 256;
            int r = idx / BN;
            int c = idx % BN;
            Bs[r][c] = We[(size_t)(k0 + r) * N + (n0 + c)];
        }
        __syncthreads();

        #pragma unroll
        for (int kk = 0; kk < BK; ++kk) {
            #pragma unroll
            for (int i = 0; i < TM; ++i) ra[i] = As[kk][trow * TM + i];
            #pragma unroll
            for (int j = 0; j < TN; ++j) rb[j] = Bs[kk][tcol * TN + j];
            #pragma unroll
            for (int i = 0; i < TM; ++i)
                #pragma unroll
                for (int j = 0; j < TN; ++j)
                    acc[i][j] += ra[i] * rb[j];
        }
        __syncthreads();
    }

    // Store (vectorized: TN=8 -> two float4 per row)
    #pragma unroll
    for (int i = 0; i < TM; ++i) {
        int r = trow * TM + i;
        if (r < rows) {
            float4* dst = reinterpret_cast<float4*>(
                Ce + (size_t)r * N + n0 + tcol * TN);
            float4 v0 = make_float4(acc[i][0], acc[i][1], acc[i][2], acc[i][3]);
            float4 v1 = make_float4(acc[i][4], acc[i][5], acc[i][6], acc[i][7]);
            dst[0] = v0;
            dst[1] = v1;
        }
    }
}

// ---------------------------------------------------------------------------
// SwiGLU: buf1 <- silu(buf1) * buf2, float4 vectorized, grid-stride.
// ---------------------------------------------------------------------------
__global__ void swiglu_kernel(float* __restrict__ o1,
                              const float* __restrict__ o2,
                              size_t n4)
{
    size_t i = (size_t)blockIdx.x * blockDim.x + threadIdx.x;
    size_t stride = (size_t)gridDim.x * blockDim.x;
    float4* p1 = reinterpret_cast<float4*>(o1);
    const float4* p2 = reinterpret_cast<const float4*>(o2);
    for (; i < n4; i += stride) {
        float4 a = p1[i];
        float4 b = p2[i];
        a.x = a.x / (1.f + __expf(-a.x)) * b.x;
        a.y = a.y / (1.f + __expf(-a.y)) * b.y;
        a.z = a.z / (1.f + __expf(-a.z)) * b.z;
        a.w = a.w / (1.f + __expf(-a.w)) * b.w;
        p1[i] = a;
    }
}

// ---------------------------------------------------------------------------
// kernel_launch: gate-GEMM, up-GEMM, SwiGLU, down-GEMM. All graph-capturable.
// ---------------------------------------------------------------------------
extern "C" void kernel_launch(void* const* d_in, const int* in_sizes, int n_in,
                              void* d_out, int out_size)
{
    const float* x    = (const float*)d_in[0];   // [T, H]
    const float* gate = (const float*)d_in[1];   // [E, H, I]
    const float* up   = (const float*)d_in[2];   // [E, H, I]
    const float* down = (const float*)d_in[3];   // [E, I, H]
    const int*   tpe  = (const int*)d_in[4];     // [E]
    float* out = (float*)d_out;                  // [T, H]

    const int E = in_sizes[4];
    const int T = in_sizes[0] / HID;

    float *buf1, *buf2;
    cudaGetSymbolAddress((void**)&buf1, g_buf1);
    cudaGetSymbolAddress((void**)&buf2, g_buf2);

    const int mtiles = (T + BM - 1) / BM;
    dim3 blk(256);

    // GEMM 1a: o1 = x @ gate[e]   (K=H, N=I)
    dim3 g1(mtiles, INTER / BN, E);
    grouped_gemm_kernel<<<g1, blk>>>(x, gate, buf1, tpe, HID, INTER);

    // GEMM 1b: o2 = x @ up[e]
    grouped_gemm_kernel<<<g1, blk>>>(x, up, buf2, tpe, HID, INTER);

    // SwiGLU: buf1 = silu(buf1) * buf2
    size_t n4 = ((size_t)T * INTER) / 4;
    int sw_blocks = (int)((n4 + 255) / 256);
    if (sw_blocks > 8192) sw_blocks = 8192;
    swiglu_kernel<<<sw_blocks, 256>>>(buf1, buf2, n4);

    // GEMM 2: out = inter @ down[e]   (K=I, N=H)
    dim3 g2(mtiles, HID / BN, E);
    grouped_gemm_kernel<<<g2, blk>>>(buf1, down, out, tpe, INTER, HID);
}

// round 4
// speedup vs baseline: 1.0472x; 1.0472x over previous
#include <cuda_runtime.h>
#include <cuda_bf16.h>
#include <cstddef>

// Problem constants (registry shape): E=8, H=1024, I=2816, T=8192.
// T and E are derived from in_sizes at launch for robustness; H/I fixed.
#define HID 1024
#define INTER 2816
#define MAX_T 8192

// Scratch: o1/inter and o2. 92.3 MB each, static device globals (allowed).
__device__ float g_buf1[(size_t)MAX_T * INTER];
__device__ float g_buf2[(size_t)MAX_T * INTER];

// ---------------------------------------------------------------------------
// Grouped SGEMM: C[start+m0 .. ] = A[seg] * W[e], W[e] is K x N row-major.
// Block tile 128x128, BK=8, 256 threads, 8x8 per-thread microtile.
// grid = (ceil(T/128), N/128, E); blocks beyond the expert's segment exit.
// ---------------------------------------------------------------------------
#define BM 128
#define BN 128
#define BK 8
#define TM 8
#define TN 8

__global__ __launch_bounds__(256, 2)
void grouped_gemm_kernel(const float* __restrict__ A,
                         const float* __restrict__ W,
                         float* __restrict__ C,
                         const int* __restrict__ tokens_per_expert,
                         int K, int N)
{
    const int e = blockIdx.z;

    // Segment start for expert e (E is tiny; 8 cached loads).
    int start = 0;
    #pragma unroll 1
    for (int i = 0; i < e; ++i) start += tokens_per_expert[i];
    const int cnt = tokens_per_expert[e];

    const int m0 = blockIdx.x * BM;
    if (m0 >= cnt) return;                 // empty tile for this expert
    const int rows = min(BM, cnt - m0);

    const float* Ae = A + (size_t)(start + m0) * K;
    const float* We = W + (size_t)e * K * N;
    float*       Ce = C + (size_t)(start + m0) * N;
    const int n0 = blockIdx.y * BN;        // N is a multiple of BN here

    __shared__ float As[BK][BM];           // A stored transposed
    __shared__ float Bs[BK][BN];

    const int tid  = threadIdx.x;          // 0..255
    const int tcol = tid % (BN / TN);      // 0..15
    const int trow = tid / (BN / TN);      // 0..15

    float acc[TM][TN];
    #pragma unroll
    for (int i = 0; i < TM; ++i)
        #pragma unroll
        for (int j = 0; j < TN; ++j) acc[i][j] = 0.f;

    float ra[TM], rb[TN];

    for (int k0 = 0; k0 < K; k0 += BK) {
        // Load A tile: BM x BK (1024 elems, 4 per thread)
        #pragma unroll
        for (int i = 0; i < (BM * BK) / 256; ++i) {
            int idx = tid + i * 256;
            int r = idx / BK;
            int c = idx % BK;
            float v = (r < rows) ? Ae[(size_t)r * K + (k0 + c)] : 0.f;
            As[c][r] = v;
        }
        // Load B tile: BK x BN (1024 elems, 4 per thread), coalesced on N
        #pragma unroll
        for (int i = 0; i < (BK * BN) / 256; ++i) {
            int idx = tid + i * 256;
            int r = idx / BN;
            int c = idx % BN;
            Bs[r][c] = We[(size_t)(k0 + r) * N + (n0 + c)];
        }
        __syncthreads();

        #pragma unroll
        for (int kk = 0; kk < BK; ++kk) {
            #pragma unroll
            for (int i = 0; i < TM; ++i) ra[i] = As[kk][trow * TM + i];
            #pragma unroll
            for (int j = 0; j < TN; ++j) rb[j] = Bs[kk][tcol * TN + j];
            #pragma unroll
            for (int i = 0; i < TM; ++i)
                #pragma unroll
                for (int j = 0; j < TN; ++j)
                    acc[i][j] += ra[i] * rb[j];
        }
        __syncthreads();
    }

    // Store (vectorized: TN=8 -> two float4 per row)
    #pragma unroll
    for (int i = 0; i < TM; ++i) {
        int r = trow * TM + i;
        if (r < rows) {
            float4* dst = reinterpret_cast<float4*>(
                Ce + (size_t)r * N + n0 + tcol * TN);
            float4 v0 = make_float4(acc[i][0], acc[i][1], acc[i][2], acc[i][3]);
            float4 v1 = make_float4(acc[i][4], acc[i][5], acc[i][6], acc[i][7]);
            dst[0] = v0;
            dst[1] = v1;
        }
    }
}

// ---------------------------------------------------------------------------
// SwiGLU: buf1 <- silu(buf1) * buf2, float4 vectorized, grid-stride.
// ---------------------------------------------------------------------------
__global__ void swiglu_kernel(float* __restrict__ o1,
                              const float* __restrict__ o2,
                              size_t n4)
{
    size_t i = (size_t)blockIdx.x * blockDim.x + threadIdx.x;
    size_t stride = (size_t)gridDim.x * blockDim.x;
    float4* p1 = reinterpret_cast<float4*>(o1);
    const float4* p2 = reinterpret_cast<const float4*>(o2);
    for (; i < n4; i += stride) {
        float4 a = p1[i];
        float4 b = p2[i];
        a.x = a.x / (1.f + __expf(-a.x)) * b.x;
        a.y = a.y / (1.f + __expf(-a.y)) * b.y;
        a.z = a.z / (1.f + __expf(-a.z)) * b.z;
        a.w = a.w / (1.f + __expf(-a.w)) * b.w;
        p1[i] = a;
    }
}

// ---------------------------------------------------------------------------
// kernel_launch: gate-GEMM, up-GEMM, SwiGLU, down-GEMM. All graph-capturable.
// ---------------------------------------------------------------------------
extern "C" void kernel_launch(void* const* d_in, const int* in_sizes, int n_in,
                              void* d_out, int out_size)
{
    const float* x    = (const float*)d_in[0];   // [T, H]
    const float* gate = (const float*)d_in[1];   // [E, H, I]
    const float* up   = (const float*)d_in[2];   // [E, H, I]
    const float* down = (const float*)d_in[3];   // [E, I, H]
    const int*   tpe  = (const int*)d_in[4];     // [E]
    float* out = (float*)d_out;                  // [T, H]

    const int E = in_sizes[4];
    const int T = in_sizes[0] / HID;

    float *buf1, *buf2;
    cudaGetSymbolAddress((void**)&buf1, g_buf1);
    cudaGetSymbolAddress((void**)&buf2, g_buf2);

    const int mtiles = (T + BM - 1) / BM;
    dim3 blk(256);

    // GEMM 1a: o1 = x @ gate[e]   (K=H, N=I)
    dim3 g1(mtiles, INTER / BN, E);
    grouped_gemm_kernel<<<g1, blk>>>(x, gate, buf1, tpe, HID, INTER);

    // GEMM 1b: o2 = x @ up[e]
    grouped_gemm_kernel<<<g1, blk>>>(x, up, buf2, tpe, HID, INTER);

    // SwiGLU: buf1 = silu(buf1) * buf2
    size_t n4 = ((size_t)T * INTER) / 4;
    int sw_blocks = (int)((n4 + 255) / 256);
    if (sw_blocks > 8192) sw_blocks = 8192;
    swiglu_kernel<<<sw_blocks, 256>>>(buf1, buf2, n4);

    // GEMM 2: out = inter @ down[e]   (K=I, N=H)
    dim3 g2(mtiles, HID / BN, E);
    grouped_gemm_kernel<<<g2, blk>>>(buf1, down, out, tpe, INTER, HID);
}

// round 6
// speedup vs baseline: 4.1534x; 3.9662x over previous
#include <cuda_runtime.h>
#include <cuda.h>
#include <cstdint>
#include <cstddef>

#define HID    1024
#define INTER_ 2816
#define MAX_T  8192
#define NEXP   8

// ---------------------------------------------------------------------------
// Scratch (static device globals; allocation-free rule)
// ---------------------------------------------------------------------------
__device__ __align__(128) float g_xr[(size_t)MAX_T * HID];          // x, tf32-rounded
__device__ __align__(128) float g_wg[(size_t)NEXP * HID * INTER_];  // gate, tf32-rounded
__device__ __align__(128) float g_wu[(size_t)NEXP * HID * INTER_];  // up, tf32-rounded
__device__ __align__(128) float g_wd[(size_t)NEXP * HID * INTER_];  // down, tf32-rounded
__device__ __align__(128) float g_inter[(size_t)MAX_T * INTER_];    // SwiGLU out, tf32-rounded

// ---------------------------------------------------------------------------
// Helpers
// ---------------------------------------------------------------------------
__device__ __forceinline__ float round_tf32_val(float v) {
    uint32_t u;
    asm("cvt.rna.tf32.f32 %0, %1;" : "=r"(u) : "f"(v));
    return __uint_as_float(u);
}

__device__ __forceinline__ uint32_t smem_u32(const void* p) {
    uint32_t a;
    asm("{ .reg .u64 t; cvta.to.shared.u64 t, %1; cvt.u32.u64 %0, t; }" : "=r"(a) : "l"(p));
    return a;
}

#define CP_ASYNC(sm, gm) \
    asm volatile("cp.async.cg.shared.global [%0], [%1], 16;" :: "r"(sm), "l"(gm))
#define CP_COMMIT() asm volatile("cp.async.commit_group;" ::: "memory")
#define CP_WAIT2()  asm volatile("cp.async.wait_group 2;" ::: "memory")

// m16n8k8 tf32 MMA (sm_80+ PTX; runs on HMMA pipe on sm_103)
__device__ __forceinline__ void mma_tf32(float* c, const uint32_t* a, const uint32_t* b) {
    asm volatile(
        "mma.sync.aligned.m16n8k8.row.col.f32.tf32.tf32.f32 "
        "{%0,%1,%2,%3}, {%4,%5,%6,%7}, {%8,%9}, {%0,%1,%2,%3};"
        : "+f"(c[0]), "+f"(c[1]), "+f"(c[2]), "+f"(c[3])
        : "r"(a[0]), "r"(a[1]), "r"(a[2]), "r"(a[3]), "r"(b[0]), "r"(b[1]));
}

// ---------------------------------------------------------------------------
// Pre-pass: RNA-round fp32 -> tf32-valued fp32 (removes truncation bias)
// ---------------------------------------------------------------------------
__global__ void round_kernel(const float* __restrict__ in, float* __restrict__ out, size_t n4) {
    size_t i  = (size_t)blockIdx.x * blockDim.x + threadIdx.x;
    size_t st = (size_t)gridDim.x * blockDim.x;
    const float4* pi = (const float4*)in;
    float4* po = (float4*)out;
    for (; i < n4; i += st) {
        float4 v = pi[i];
        v.x = round_tf32_val(v.x); v.y = round_tf32_val(v.y);
        v.z = round_tf32_val(v.z); v.w = round_tf32_val(v.w);
        po[i] = v;
    }
}

// ---------------------------------------------------------------------------
// Tiling constants
// ---------------------------------------------------------------------------
#define BK        16
#define STAGES    4
#define A_STRIDE  20    // floats per SMEM A row (pad 16 -> 20: conflict-free frags)
#define B_STRIDE  136   // floats per SMEM B row (128 -> 136: pad 8 mod 32)
#define BD_STRIDE 264   // down: 256 -> 264
#define A_BYTES   (128 * A_STRIDE * 4)     // 10240
#define B_BYTES   (BK * B_STRIDE * 4)      // 8704
#define BD_BYTES  (BK * BD_STRIDE * 4)     // 16896
#define FS_STAGE  (A_BYTES + 2 * B_BYTES)  // 27648 (fused)
#define DS_STAGE  (A_BYTES + BD_BYTES)     // 27136 (down)

// ---------------------------------------------------------------------------
// Fused gate/up GEMM + SwiGLU.
// CTA: 128 rows x 128 cols of gate AND 128 x 128 of up (same n-range).
// 8 warps: warp = 64 rows x 32 cols per matrix (16 mma/kstep/warp x 2 mats).
// ---------------------------------------------------------------------------
__device__ __forceinline__ void load_stage_fused(
    float* sbuf, int tid, int rows,
    const float* Ag, const float* Gg, const float* Ug, int k0)
{
    float* sA = sbuf;
    float* sG = sA + A_BYTES / 4;
    float* sU = sG + B_BYTES / 4;
    #pragma unroll
    for (int j = 0; j < 2; ++j) {                 // A: 128x16, 512 16B chunks
        int idx = tid + j * 256;
        int r = idx >> 2, c = idx & 3;
        int gr = (r < rows) ? r : 0;
        CP_ASYNC(smem_u32(sA + r * A_STRIDE + c * 4),
                 Ag + (size_t)gr * HID + k0 + c * 4);
    }
    #pragma unroll
    for (int j = 0; j < 2; ++j) {                 // Bg: 16x128
        int idx = tid + j * 256;
        int r = idx >> 5, c = idx & 31;
        CP_ASYNC(smem_u32(sG + r * B_STRIDE + c * 4),
                 Gg + (size_t)(k0 + r) * INTER_ + c * 4);
    }
    #pragma unroll
    for (int j = 0; j < 2; ++j) {                 // Bu: 16x128
        int idx = tid + j * 256;
        int r = idx >> 5, c = idx & 31;
        CP_ASYNC(smem_u32(sU + r * B_STRIDE + c * 4),
                 Ug + (size_t)(k0 + r) * INTER_ + c * 4);
    }
}

__device__ __forceinline__ void compute_stage_fused(
    const float* sbuf, int wm, int wn, int lane,
    float cg[4][4][4], float cu[4][4][4])
{
    const float* sA = sbuf;
    const float* sG = sA + A_BYTES / 4;
    const float* sU = sG + B_BYTES / 4;
    #pragma unroll
    for (int ks = 0; ks < 2; ++ks) {
        uint32_t af[4][4];
        const int ar = wm * 64 + (lane >> 2);
        const int ac = ks * 8 + (lane & 3);
        #pragma unroll
        for (int mt = 0; mt < 4; ++mt) {
            const float* p = sA + (ar + mt * 16) * A_STRIDE + ac;
            af[mt][0] = __float_as_uint(p[0]);
            af[mt][1] = __float_as_uint(p[8 * A_STRIDE]);
            af[mt][2] = __float_as_uint(p[4]);
            af[mt][3] = __float_as_uint(p[8 * A_STRIDE + 4]);
        }
        uint32_t bg[4][2], bu[4][2];
        const int br = ks * 8 + (lane & 3);
        const int bc = wn * 32 + (lane >> 2);
        #pragma unroll
        for (int nt = 0; nt < 4; ++nt) {
            const float* pg = sG + br * B_STRIDE + bc + nt * 8;
            bg[nt][0] = __float_as_uint(pg[0]);
            bg[nt][1] = __float_as_uint(pg[4 * B_STRIDE]);
            const float* pu = sU + br * B_STRIDE + bc + nt * 8;
            bu[nt][0] = __float_as_uint(pu[0]);
            bu[nt][1] = __float_as_uint(pu[4 * B_STRIDE]);
        }
        #pragma unroll
        for (int mt = 0; mt < 4; ++mt)
            #pragma unroll
            for (int nt = 0; nt < 4; ++nt) {
                mma_tf32(cg[mt][nt], af[mt], bg[nt]);
                mma_tf32(cu[mt][nt], af[mt], bu[nt]);
            }
    }
}

__global__ __launch_bounds__(256, 1)
void fused_gate_up(const float* __restrict__ X, const float* __restrict__ WG,
                   const float* __restrict__ WU, float* __restrict__ OUT,
                   const int* __restrict__ tpe)
{
    const int e = blockIdx.z;
    int start = 0;
    #pragma unroll
    for (int i = 0; i < NEXP; ++i) if (i < e) start += tpe[i];
    const int cnt = tpe[e];
    const int m0 = blockIdx.x * 128;
    if (m0 >= cnt) return;
    const int rows = min(128, cnt - m0);
    const int n0 = blockIdx.y * 128;

    extern __shared__ float sm[];
    const int tid = threadIdx.x, wid = tid >> 5, lane = tid & 31;
    const int wm = wid & 1, wn = wid >> 1;

    const float* Ag = X  + (size_t)(start + m0) * HID;
    const float* Gg = WG + (size_t)e * HID * INTER_ + n0;
    const float* Ug = WU + (size_t)e * HID * INTER_ + n0;

    float cg[4][4][4], cu[4][4][4];
    #pragma unroll
    for (int a = 0; a < 4; ++a)
        #pragma unroll
        for (int b = 0; b < 4; ++b)
            #pragma unroll
            for (int c = 0; c < 4; ++c) { cg[a][b][c] = 0.f; cu[a][b][c] = 0.f; }

    const int niter = HID / BK;  // 64
    #pragma unroll
    for (int s = 0; s < STAGES - 1; ++s) {
        load_stage_fused(sm + s * (FS_STAGE / 4), tid, rows, Ag, Gg, Ug, s * BK);
        CP_COMMIT();
    }
    for (int i = 0; i < niter; ++i) {
        CP_WAIT2();
        __syncthreads();
        compute_stage_fused(sm + (i % STAGES) * (FS_STAGE / 4), wm, wn, lane, cg, cu);
        __syncthreads();
        const int nb = i + STAGES - 1;
        if (nb < niter)
            load_stage_fused(sm + (nb % STAGES) * (FS_STAGE / 4), tid, rows, Ag, Gg, Ug, nb * BK);
        CP_COMMIT();
    }

    // Epilogue: SwiGLU, tf32-round, store (float2 = paired cols)
    const int rbase = wm * 64 + (lane >> 2);
    const int cbase = n0 + wn * 32 + 2 * (lane & 3);
    #pragma unroll
    for (int mt = 0; mt < 4; ++mt) {
        #pragma unroll
        for (int nt = 0; nt < 4; ++nt) {
            const int r0 = rbase + mt * 16;
            const int c  = cbase + nt * 8;
            if (r0 < rows) {
                float a0 = cg[mt][nt][0], a1 = cg[mt][nt][1];
                float2 v;
                v.x = round_tf32_val(a0 / (1.f + __expf(-a0)) * cu[mt][nt][0]);
                v.y = round_tf32_val(a1 / (1.f + __expf(-a1)) * cu[mt][nt][1]);
                *reinterpret_cast<float2*>(OUT + (size_t)(start + m0 + r0) * INTER_ + c) = v;
            }
            if (r0 + 8 < rows) {
                float a2 = cg[mt][nt][2], a3 = cg[mt][nt][3];
                float2 v;
                v.x = round_tf32_val(a2 / (1.f + __expf(-a2)) * cu[mt][nt][2]);
                v.y = round_tf32_val(a3 / (1.f + __expf(-a3)) * cu[mt][nt][3]);
                *reinterpret_cast<float2*>(OUT + (size_t)(start + m0 + r0 + 8) * INTER_ + c) = v;
            }
        }
    }
}

// ---------------------------------------------------------------------------
// Down-proj GEMM: out = inter @ down.  CTA 128 x 256, warp 64 x 64.
// ---------------------------------------------------------------------------
__device__ __forceinline__ void load_stage_down(
    float* sbuf, int tid, int rows,
    const float* Ag, const float* Bg, int k0)
{
    float* sA = sbuf;
    float* sB = sA + A_BYTES / 4;
    #pragma unroll
    for (int j = 0; j < 2; ++j) {                 // A: 128x16
        int idx = tid + j * 256;
        int r = idx >> 2, c = idx & 3;
        int gr = (r < rows) ? r : 0;
        CP_ASYNC(smem_u32(sA + r * A_STRIDE + c * 4),
                 Ag + (size_t)gr * INTER_ + k0 + c * 4);
    }
    #pragma unroll
    for (int j = 0; j < 4; ++j) {                 // B: 16x256
        int idx = tid + j * 256;
        int r = idx >> 6, c = idx & 63;
        CP_ASYNC(smem_u32(sB + r * BD_STRIDE + c * 4),
                 Bg + (size_t)(k0 + r) * HID + c * 4);
    }
}

__device__ __forceinline__ void compute_stage_down(
    const float* sbuf, int wm, int wn, int lane, float cc[4][8][4])
{
    const float* sA = sbuf;
    const float* sB = sA + A_BYTES / 4;
    #pragma unroll
    for (int ks = 0; ks < 2; ++ks) {
        uint32_t af[4][4];
        const int ar = wm * 64 + (lane >> 2);
        const int ac = ks * 8 + (lane & 3);
        #pragma unroll
        for (int mt = 0; mt < 4; ++mt) {
            const float* p = sA + (ar + mt * 16) * A_STRIDE + ac;
            af[mt][0] = __float_as_uint(p[0]);
            af[mt][1] = __float_as_uint(p[8 * A_STRIDE]);
            af[mt][2] = __float_as_uint(p[4]);
            af[mt][3] = __float_as_uint(p[8 * A_STRIDE + 4]);
        }
        uint32_t bf[8][2];
        const int br = ks * 8 + (lane & 3);
        const int bc = wn * 64 + (lane >> 2);
        #pragma unroll
        for (int nt = 0; nt < 8; ++nt) {
            const float* pb = sB + br * BD_STRIDE + bc + nt * 8;
            bf[nt][0] = __float_as_uint(pb[0]);
            bf[nt][1] = __float_as_uint(pb[4 * BD_STRIDE]);
        }
        #pragma unroll
        for (int mt = 0; mt < 4; ++mt)
            #pragma unroll
            for (int nt = 0; nt < 8; ++nt)
                mma_tf32(cc[mt][nt], af[mt], bf[nt]);
    }
}

__global__ __launch_bounds__(256, 1)
void down_proj(const float* __restrict__ X, const float* __restrict__ WD,
               float* __restrict__ OUT, const int* __restrict__ tpe)
{
    const int e = blockIdx.z;
    int start = 0;
    #pragma unroll
    for (int i = 0; i < NEXP; ++i) if (i < e) start += tpe[i];
    const int cnt = tpe[e];
    const int m0 = blockIdx.x * 128;
    if (m0 >= cnt) return;
    const int rows = min(128, cnt - m0);
    const int n0 = blockIdx.y * 256;

    extern __shared__ float sm[];
    const int tid = threadIdx.x, wid = tid >> 5, lane = tid & 31;
    const int wm = wid & 1, wn = wid >> 1;

    const float* Ag = X  + (size_t)(start + m0) * INTER_;
    const float* Bg = WD + (size_t)e * INTER_ * HID + n0;

    float cc[4][8][4];
    #pragma unroll
    for (int a = 0; a < 4; ++a)
        #pragma unroll
        for (int b = 0; b < 8; ++b)
            #pragma unroll
            for (int c = 0; c < 4; ++c) cc[a][b][c] = 0.f;

    const int niter = INTER_ / BK;  // 176
    #pragma unroll
    for (int s = 0; s < STAGES - 1; ++s) {
        load_stage_down(sm + s * (DS_STAGE / 4), tid, rows, Ag, Bg, s * BK);
        CP_COMMIT();
    }
    for (int i = 0; i < niter; ++i) {
        CP_WAIT2();
        __syncthreads();
        compute_stage_down(sm + (i % STAGES) * (DS_STAGE / 4), wm, wn, lane, cc);
        __syncthreads();
        const int nb = i + STAGES - 1;
        if (nb < niter)
            load_stage_down(sm + (nb % STAGES) * (DS_STAGE / 4), tid, rows, Ag, Bg, nb * BK);
        CP_COMMIT();
    }

    const int rbase = wm * 64 + (lane >> 2);
    const int cbase = n0 + wn * 64 + 2 * (lane & 3);
    #pragma unroll
    for (int mt = 0; mt < 4; ++mt) {
        #pragma unroll
        for (int nt = 0; nt < 8; ++nt) {
            const int r0 = rbase + mt * 16;
            const int c  = cbase + nt * 8;
            if (r0 < rows) {
                float2 v = make_float2(cc[mt][nt][0], cc[mt][nt][1]);
                *reinterpret_cast<float2*>(OUT + (size_t)(start + m0 + r0) * HID + c) = v;
            }
            if (r0 + 8 < rows) {
                float2 v = make_float2(cc[mt][nt][2], cc[mt][nt][3]);
                *reinterpret_cast<float2*>(OUT + (size_t)(start + m0 + r0 + 8) * HID + c) = v;
            }
        }
    }
}

// ---------------------------------------------------------------------------
// Host side
// ---------------------------------------------------------------------------
extern "C" void kernel_launch(void* const* d_in, const int* in_sizes, int n_in,
                              void* d_out, int out_size)
{
    const float* x    = (const float*)d_in[0];   // [T, H]
    const float* gate = (const float*)d_in[1];   // [E, H, I]
    const float* up   = (const float*)d_in[2];   // [E, H, I]
    const float* down = (const float*)d_in[3];   // [E, I, H]
    const int*   tpe  = (const int*)d_in[4];     // [E]
    float* out = (float*)d_out;                  // [T, H]

    const int T = in_sizes[0] / HID;
    const size_t wsz = (size_t)NEXP * HID * INTER_;

    float *xr, *wg, *wu, *wd, *inter;
    cudaGetSymbolAddress((void**)&xr, g_xr);
    cudaGetSymbolAddress((void**)&wg, g_wg);
    cudaGetSymbolAddress((void**)&wu, g_wu);
    cudaGetSymbolAddress((void**)&wd, g_wd);
    cudaGetSymbolAddress((void**)&inter, g_inter);

    // Pre-pass: RNA-round all GEMM operands to tf32 values
    round_kernel<<<2048, 256>>>(x,    xr, (size_t)T * HID / 4);
    round_kernel<<<4096, 256>>>(gate, wg, wsz / 4);
    round_kernel<<<4096, 256>>>(up,   wu, wsz / 4);
    round_kernel<<<4096, 256>>>(down, wd, wsz / 4);

    cudaFuncSetAttribute(fused_gate_up, cudaFuncAttributeMaxDynamicSharedMemorySize,
                         STAGES * FS_STAGE);
    cudaFuncSetAttribute(down_proj, cudaFuncAttributeMaxDynamicSharedMemorySize,
                         STAGES * DS_STAGE);

    const int mtiles = (T + 127) / 128;

    dim3 g1(mtiles, INTER_ / 128, NEXP);
    fused_gate_up<<<g1, 256, STAGES * FS_STAGE>>>(xr, wg, wu, inter, tpe);

    dim3 g2(mtiles, HID / 256, NEXP);
    down_proj<<<g2, 256, STAGES * DS_STAGE>>>(inter, wd, out, tpe);
}

// round 7
// speedup vs baseline: 6.9279x; 1.6680x over previous
#include <cuda_runtime.h>
#include <cuda.h>
#include <cuda_fp16.h>
#include <cstdint>
#include <cstddef>

#define HID    1024
#define INTER_ 2816
#define MAX_T  8192
#define NEXP   8

// ---------------------------------------------------------------------------
// Scratch (static device globals; allocation-free rule)
// ---------------------------------------------------------------------------
__device__ __align__(128) __half g_xh[(size_t)MAX_T * HID];          // x -> fp16 (RN)
__device__ __align__(128) __half g_wg[(size_t)NEXP * HID * INTER_];  // gate fp16
__device__ __align__(128) __half g_wu[(size_t)NEXP * HID * INTER_];  // up fp16
__device__ __align__(128) __half g_wd[(size_t)NEXP * HID * INTER_];  // down fp16
__device__ __align__(128) __half g_inter[(size_t)MAX_T * INTER_];    // SwiGLU out fp16

// ---------------------------------------------------------------------------
// Helpers
// ---------------------------------------------------------------------------
__device__ __forceinline__ uint32_t smem_u32(const void* p) {
    uint32_t a;
    asm("{ .reg .u64 t; cvta.to.shared.u64 t, %1; cvt.u32.u64 %0, t; }" : "=r"(a) : "l"(p));
    return a;
}

__device__ __forceinline__ uint32_t f22u(float a, float b) {
    __half2 h = __floats2half2_rn(a, b);
    return *reinterpret_cast<uint32_t*>(&h);
}

#define CP_ASYNC(sm, gm) \
    asm volatile("cp.async.cg.shared.global [%0], [%1], 16;" :: "r"(sm), "l"(gm))
#define CP_COMMIT() asm volatile("cp.async.commit_group;" ::: "memory")
#define CP_WAIT2()  asm volatile("cp.async.wait_group 2;" ::: "memory")

// m16n8k16 fp16 MMA, fp32 accum (sm_80+ PTX; HMMA pipe on sm_103)
__device__ __forceinline__ void mma_f16(float* c, const uint32_t* a, const uint32_t* b) {
    asm volatile(
        "mma.sync.aligned.m16n8k16.row.col.f32.f16.f16.f32 "
        "{%0,%1,%2,%3}, {%4,%5,%6,%7}, {%8,%9}, {%0,%1,%2,%3};"
        : "+f"(c[0]), "+f"(c[1]), "+f"(c[2]), "+f"(c[3])
        : "r"(a[0]), "r"(a[1]), "r"(a[2]), "r"(a[3]), "r"(b[0]), "r"(b[1]));
}

// ---------------------------------------------------------------------------
// Pre-pass: fp32 -> fp16 RN convert (8 floats -> 8 halves per thread-iter)
// ---------------------------------------------------------------------------
__global__ void cvt_half_kernel(const float* __restrict__ in, __half* __restrict__ out,
                                size_t n8) {
    size_t i  = (size_t)blockIdx.x * blockDim.x + threadIdx.x;
    size_t st = (size_t)gridDim.x * blockDim.x;
    const float4* pi = (const float4*)in;
    uint4* po = (uint4*)out;
    for (; i < n8; i += st) {
        float4 a = pi[2 * i];
        float4 b = pi[2 * i + 1];
        uint4 v;
        v.x = f22u(a.x, a.y);
        v.y = f22u(a.z, a.w);
        v.z = f22u(b.x, b.y);
        v.w = f22u(b.z, b.w);
        po[i] = v;
    }
}

// ---------------------------------------------------------------------------
// Tiling constants (halves)
// ---------------------------------------------------------------------------
#define BK        32     // halves of K per stage (2 x k16 mma steps)
#define STAGES    4
#define A_STRIDE  40     // halves per SMEM A row (32 + 8 pad) -> conflict-free frags
#define B_STRIDE  136    // halves per SMEM B row (128 + 8)
#define BD_STRIDE 264    // down: 256 + 8
#define A_BYTES   (128 * A_STRIDE * 2)     // 10240
#define B_BYTES   (BK * B_STRIDE * 2)      // 8704
#define BD_BYTES  (BK * BD_STRIDE * 2)     // 16896
#define FS_STAGE  (A_BYTES + 2 * B_BYTES)  // 27648
#define DS_STAGE  (A_BYTES + BD_BYTES)     // 27136

// ---------------------------------------------------------------------------
// Fused gate/up GEMM + SwiGLU.  CTA 128 x 128 (both matrices share A tile).
// 8 warps: wm in {0,1} x wn in {0..3}; warp tile 64 x 32 per matrix.
// ---------------------------------------------------------------------------
__device__ __forceinline__ void load_stage_fused(
    __half* sbuf, int tid, int rows,
    const __half* Ag, const __half* Gg, const __half* Ug, int k0)
{
    __half* sA = sbuf;
    __half* sG = sA + A_BYTES / 2;
    __half* sU = sG + B_BYTES / 2;
    #pragma unroll
    for (int j = 0; j < 2; ++j) {                 // A: 128 x 32 halves, 512 chunks
        int idx = tid + j * 256;
        int r = idx >> 2, c = idx & 3;            // 4 chunks of 8 halves per row
        int gr = (r < rows) ? r : 0;
        CP_ASYNC(smem_u32(sA + r * A_STRIDE + c * 8),
                 Ag + (size_t)gr * HID + k0 + c * 8);
    }
    #pragma unroll
    for (int j = 0; j < 2; ++j) {                 // Bg: 32 x 128 halves, 512 chunks
        int idx = tid + j * 256;
        int r = idx >> 4, c = idx & 15;
        CP_ASYNC(smem_u32(sG + r * B_STRIDE + c * 8),
                 Gg + (size_t)(k0 + r) * INTER_ + c * 8);
    }
    #pragma unroll
    for (int j = 0; j < 2; ++j) {                 // Bu: 32 x 128 halves
        int idx = tid + j * 256;
        int r = idx >> 4, c = idx & 15;
        CP_ASYNC(smem_u32(sU + r * B_STRIDE + c * 8),
                 Ug + (size_t)(k0 + r) * INTER_ + c * 8);
    }
}

__device__ __forceinline__ void compute_stage_fused(
    const __half* sbuf, int wm, int wn, int lane,
    float cg[4][4][4], float cu[4][4][4])
{
    const __half* sA = sbuf;
    const unsigned short* sG = (const unsigned short*)(sA + A_BYTES / 2);
    const unsigned short* sU = sG + B_BYTES / 2;
    #pragma unroll
    for (int ks = 0; ks < 2; ++ks) {
        uint32_t af[4][4];
        const int ar = wm * 64 + (lane >> 2);
        const int ac = ks * 16 + 2 * (lane & 3);
        #pragma unroll
        for (int mt = 0; mt < 4; ++mt) {
            const __half* p = sA + (ar + mt * 16) * A_STRIDE + ac;
            af[mt][0] = *(const uint32_t*)(p);
            af[mt][1] = *(const uint32_t*)(p + 8 * A_STRIDE);
            af[mt][2] = *(const uint32_t*)(p + 8);
            af[mt][3] = *(const uint32_t*)(p + 8 * A_STRIDE + 8);
        }
        uint32_t bg[4][2], bu[4][2];
        const int br = ks * 16 + 2 * (lane & 3);
        const int bc = wn * 32 + (lane >> 2);
        #pragma unroll
        for (int nt = 0; nt < 4; ++nt) {
            const unsigned short* pg = sG + br * B_STRIDE + bc + nt * 8;
            bg[nt][0] = (uint32_t)pg[0]              | ((uint32_t)pg[B_STRIDE]     << 16);
            bg[nt][1] = (uint32_t)pg[8 * B_STRIDE]   | ((uint32_t)pg[9 * B_STRIDE] << 16);
            const unsigned short* pu = sU + br * B_STRIDE + bc + nt * 8;
            bu[nt][0] = (uint32_t)pu[0]              | ((uint32_t)pu[B_STRIDE]     << 16);
            bu[nt][1] = (uint32_t)pu[8 * B_STRIDE]   | ((uint32_t)pu[9 * B_STRIDE] << 16);
        }
        #pragma unroll
        for (int mt = 0; mt < 4; ++mt)
            #pragma unroll
            for (int nt = 0; nt < 4; ++nt) {
                mma_f16(cg[mt][nt], af[mt], bg[nt]);
                mma_f16(cu[mt][nt], af[mt], bu[nt]);
            }
    }
}

__global__ __launch_bounds__(256, 1)
void fused_gate_up(const __half* __restrict__ X, const __half* __restrict__ WG,
                   const __half* __restrict__ WU, __half* __restrict__ OUT,
                   const int* __restrict__ tpe)
{
    const int e = blockIdx.z;
    int start = 0;
    #pragma unroll
    for (int i = 0; i < NEXP; ++i) if (i < e) start += tpe[i];
    const int cnt = tpe[e];
    const int m0 = blockIdx.x * 128;
    if (m0 >= cnt) return;
    const int rows = min(128, cnt - m0);
    const int n0 = blockIdx.y * 128;

    extern __shared__ __half sm[];
    const int tid = threadIdx.x, wid = tid >> 5, lane = tid & 31;
    const int wm = wid & 1, wn = wid >> 1;

    const __half* Ag = X  + (size_t)(start + m0) * HID;
    const __half* Gg = WG + (size_t)e * HID * INTER_ + n0;
    const __half* Ug = WU + (size_t)e * HID * INTER_ + n0;

    float cg[4][4][4], cu[4][4][4];
    #pragma unroll
    for (int a = 0; a < 4; ++a)
        #pragma unroll
        for (int b = 0; b < 4; ++b)
            #pragma unroll
            for (int c = 0; c < 4; ++c) { cg[a][b][c] = 0.f; cu[a][b][c] = 0.f; }

    const int niter = HID / BK;  // 32
    #pragma unroll
    for (int s = 0; s < STAGES - 1; ++s) {
        load_stage_fused(sm + s * (FS_STAGE / 2), tid, rows, Ag, Gg, Ug, s * BK);
        CP_COMMIT();
    }
    for (int i = 0; i < niter; ++i) {
        CP_WAIT2();
        __syncthreads();
        compute_stage_fused(sm + (i % STAGES) * (FS_STAGE / 2), wm, wn, lane, cg, cu);
        __syncthreads();
        const int nb = i + STAGES - 1;
        if (nb < niter)
            load_stage_fused(sm + (nb % STAGES) * (FS_STAGE / 2), tid, rows, Ag, Gg, Ug, nb * BK);
        CP_COMMIT();
    }

    // Epilogue: SwiGLU, convert to fp16 (RN), store packed half2
    const int rbase = wm * 64 + (lane >> 2);
    const int cbase = n0 + wn * 32 + 2 * (lane & 3);
    #pragma unroll
    for (int mt = 0; mt < 4; ++mt) {
        #pragma unroll
        for (int nt = 0; nt < 4; ++nt) {
            const int r0 = rbase + mt * 16;
            const int c  = cbase + nt * 8;
            if (r0 < rows) {
                float a0 = cg[mt][nt][0], a1 = cg[mt][nt][1];
                uint32_t v = f22u(a0 / (1.f + __expf(-a0)) * cu[mt][nt][0],
                                  a1 / (1.f + __expf(-a1)) * cu[mt][nt][1]);
                *(uint32_t*)(OUT + (size_t)(start + m0 + r0) * INTER_ + c) = v;
            }
            if (r0 + 8 < rows) {
                float a2 = cg[mt][nt][2], a3 = cg[mt][nt][3];
                uint32_t v = f22u(a2 / (1.f + __expf(-a2)) * cu[mt][nt][2],
                                  a3 / (1.f + __expf(-a3)) * cu[mt][nt][3]);
                *(uint32_t*)(OUT + (size_t)(start + m0 + r0 + 8) * INTER_ + c) = v;
            }
        }
    }
}

// ---------------------------------------------------------------------------
// Down-proj GEMM: out(fp32) = inter(fp16) @ down(fp16).  CTA 128 x 256.
// ---------------------------------------------------------------------------
__device__ __forceinline__ void load_stage_down(
    __half* sbuf, int tid, int rows,
    const __half* Ag, const __half* Bg, int k0)
{
    __half* sA = sbuf;
    __half* sB = sA + A_BYTES / 2;
    #pragma unroll
    for (int j = 0; j < 2; ++j) {                 // A: 128 x 32 halves
        int idx = tid + j * 256;
        int r = idx >> 2, c = idx & 3;
        int gr = (r < rows) ? r : 0;
        CP_ASYNC(smem_u32(sA + r * A_STRIDE + c * 8),
                 Ag + (size_t)gr * INTER_ + k0 + c * 8);
    }
    #pragma unroll
    for (int j = 0; j < 4; ++j) {                 // B: 32 x 256 halves, 1024 chunks
        int idx = tid + j * 256;
        int r = idx >> 5, c = idx & 31;
        CP_ASYNC(smem_u32(sB + r * BD_STRIDE + c * 8),
                 Bg + (size_t)(k0 + r) * HID + c * 8);
    }
}

__device__ __forceinline__ void compute_stage_down(
    const __half* sbuf, int wm, int wn, int lane, float cc[4][8][4])
{
    const __half* sA = sbuf;
    const unsigned short* sB = (const unsigned short*)(sA + A_BYTES / 2);
    #pragma unroll
    for (int ks = 0; ks < 2; ++ks) {
        uint32_t af[4][4];
        const int ar = wm * 64 + (lane >> 2);
        const int ac = ks * 16 + 2 * (lane & 3);
        #pragma unroll
        for (int mt = 0; mt < 4; ++mt) {
            const __half* p = sA + (ar + mt * 16) * A_STRIDE + ac;
            af[mt][0] = *(const uint32_t*)(p);
            af[mt][1] = *(const uint32_t*)(p + 8 * A_STRIDE);
            af[mt][2] = *(const uint32_t*)(p + 8);
            af[mt][3] = *(const uint32_t*)(p + 8 * A_STRIDE + 8);
        }
        uint32_t bf[8][2];
        const int br = ks * 16 + 2 * (lane & 3);
        const int bc = wn * 64 + (lane >> 2);
        #pragma unroll
        for (int nt = 0; nt < 8; ++nt) {
            const unsigned short* pb = sB + br * BD_STRIDE + bc + nt * 8;
            bf[nt][0] = (uint32_t)pb[0]             | ((uint32_t)pb[BD_STRIDE]     << 16);
            bf[nt][1] = (uint32_t)pb[8 * BD_STRIDE] | ((uint32_t)pb[9 * BD_STRIDE] << 16);
        }
        #pragma unroll
        for (int mt = 0; mt < 4; ++mt)
            #pragma unroll
            for (int nt = 0; nt < 8; ++nt)
                mma_f16(cc[mt][nt], af[mt], bf[nt]);
    }
}

__global__ __launch_bounds__(256, 1)
void down_proj(const __half* __restrict__ X, const __half* __restrict__ WD,
               float* __restrict__ OUT, const int* __restrict__ tpe)
{
    const int e = blockIdx.z;
    int start = 0;
    #pragma unroll
    for (int i = 0; i < NEXP; ++i) if (i < e) start += tpe[i];
    const int cnt = tpe[e];
    const int m0 = blockIdx.x * 128;
    if (m0 >= cnt) return;
    const int rows = min(128, cnt - m0);
    const int n0 = blockIdx.y * 256;

    extern __shared__ __half sm[];
    const int tid = threadIdx.x, wid = tid >> 5, lane = tid & 31;
    const int wm = wid & 1, wn = wid >> 1;

    const __half* Ag = X  + (size_t)(start + m0) * INTER_;
    const __half* Bg = WD + (size_t)e * INTER_ * HID + n0;

    float cc[4][8][4];
    #pragma unroll
    for (int a = 0; a < 4; ++a)
        #pragma unroll
        for (int b = 0; b < 8; ++b)
            #pragma unroll
            for (int c = 0; c < 4; ++c) cc[a][b][c] = 0.f;

    const int niter = INTER_ / BK;  // 88
    #pragma unroll
    for (int s = 0; s < STAGES - 1; ++s) {
        load_stage_down(sm + s * (DS_STAGE / 2), tid, rows, Ag, Bg, s * BK);
        CP_COMMIT();
    }
    for (int i = 0; i < niter; ++i) {
        CP_WAIT2();
        __syncthreads();
        compute_stage_down(sm + (i % STAGES) * (DS_STAGE / 2), wm, wn, lane, cc);
        __syncthreads();
        const int nb = i + STAGES - 1;
        if (nb < niter)
            load_stage_down(sm + (nb % STAGES) * (DS_STAGE / 2), tid, rows, Ag, Bg, nb * BK);
        CP_COMMIT();
    }

    const int rbase = wm * 64 + (lane >> 2);
    const int cbase = n0 + wn * 64 + 2 * (lane & 3);
    #pragma unroll
    for (int mt = 0; mt < 4; ++mt) {
        #pragma unroll
        for (int nt = 0; nt < 8; ++nt) {
            const int r0 = rbase + mt * 16;
            const int c  = cbase + nt * 8;
            if (r0 < rows) {
                float2 v = make_float2(cc[mt][nt][0], cc[mt][nt][1]);
                *reinterpret_cast<float2*>(OUT + (size_t)(start + m0 + r0) * HID + c) = v;
            }
            if (r0 + 8 < rows) {
                float2 v = make_float2(cc[mt][nt][2], cc[mt][nt][3]);
                *reinterpret_cast<float2*>(OUT + (size_t)(start + m0 + r0 + 8) * HID + c) = v;
            }
        }
    }
}

// ---------------------------------------------------------------------------
// Host side
// ---------------------------------------------------------------------------
extern "C" void kernel_launch(void* const* d_in, const int* in_sizes, int n_in,
                              void* d_out, int out_size)
{
    const float* x    = (const float*)d_in[0];   // [T, H]
    const float* gate = (const float*)d_in[1];   // [E, H, I]
    const float* up   = (const float*)d_in[2];   // [E, H, I]
    const float* down = (const float*)d_in[3];   // [E, I, H]
    const int*   tpe  = (const int*)d_in[4];     // [E]
    float* out = (float*)d_out;                  // [T, H]

    const int T = in_sizes[0] / HID;
    const size_t wsz = (size_t)NEXP * HID * INTER_;

    __half *xh, *wg, *wu, *wd, *inter;
    cudaGetSymbolAddress((void**)&xh, g_xh);
    cudaGetSymbolAddress((void**)&wg, g_wg);
    cudaGetSymbolAddress((void**)&wu, g_wu);
    cudaGetSymbolAddress((void**)&wd, g_wd);
    cudaGetSymbolAddress((void**)&inter, g_inter);

    // Pre-pass: fp32 -> fp16 RN conversion of all GEMM operands
    cvt_half_kernel<<<1024, 256>>>(x,    xh, (size_t)T * HID / 8);
    cvt_half_kernel<<<4096, 256>>>(gate, wg, wsz / 8);
    cvt_half_kernel<<<4096, 256>>>(up,   wu, wsz / 8);
    cvt_half_kernel<<<4096, 256>>>(down, wd, wsz / 8);

    cudaFuncSetAttribute(fused_gate_up, cudaFuncAttributeMaxDynamicSharedMemorySize,
                         STAGES * FS_STAGE);
    cudaFuncSetAttribute(down_proj, cudaFuncAttributeMaxDynamicSharedMemorySize,
                         STAGES * DS_STAGE);

    const int mtiles = (T + 127) / 128;

    dim3 g1(mtiles, INTER_ / 128, NEXP);
    fused_gate_up<<<g1, 256, STAGES * FS_STAGE>>>(xh, wg, wu, inter, tpe);

    dim3 g2(mtiles, HID / 256, NEXP);
    down_proj<<<g2, 256, STAGES * DS_STAGE>>>(inter, wd, out, tpe);
}

// round 8
// speedup vs baseline: 7.0494x; 1.0175x over previous
#include <cuda_runtime.h>
#include <cuda.h>
#include <cuda_fp16.h>
#include <cstdint>
#include <cstddef>

#define HID    1024
#define INTER_ 2816
#define MAX_T  8192
#define NEXP   8

// ---------------------------------------------------------------------------
// Scratch (static device globals; allocation-free rule)
// Weights stored TRANSPOSED: [E][N][K], K contiguous.
// ---------------------------------------------------------------------------
__device__ __align__(128) __half g_xh[(size_t)MAX_T * HID];          // x fp16 [T][H]
__device__ __align__(128) __half g_wg[(size_t)NEXP * HID * INTER_];  // gate^T [E][I][H]
__device__ __align__(128) __half g_wu[(size_t)NEXP * HID * INTER_];  // up^T   [E][I][H]
__device__ __align__(128) __half g_wd[(size_t)NEXP * HID * INTER_];  // down^T [E][H][I]
__device__ __align__(128) __half g_inter[(size_t)MAX_T * INTER_];    // [T][I]

// ---------------------------------------------------------------------------
// Helpers
// ---------------------------------------------------------------------------
__device__ __forceinline__ uint32_t smem_u32(const void* p) {
    uint32_t a;
    asm("{ .reg .u64 t; cvta.to.shared.u64 t, %1; cvt.u32.u64 %0, t; }" : "=r"(a) : "l"(p));
    return a;
}

__device__ __forceinline__ uint32_t f22u(float a, float b) {
    __half2 h = __floats2half2_rn(a, b);
    return *reinterpret_cast<uint32_t*>(&h);
}

#define CP_ASYNC(sm, gm) \
    asm volatile("cp.async.cg.shared.global [%0], [%1], 16;" :: "r"(sm), "l"(gm))
#define CP_COMMIT() asm volatile("cp.async.commit_group;" ::: "memory")
#define CP_WAIT2()  asm volatile("cp.async.wait_group 2;" ::: "memory")

__device__ __forceinline__ void ldm_x4(uint32_t& r0, uint32_t& r1, uint32_t& r2,
                                       uint32_t& r3, uint32_t addr) {
    asm volatile("ldmatrix.sync.aligned.m8n8.x4.shared.b16 {%0,%1,%2,%3}, [%4];"
                 : "=r"(r0), "=r"(r1), "=r"(r2), "=r"(r3) : "r"(addr));
}

// m16n8k16 fp16 MMA, fp32 accum
__device__ __forceinline__ void mma_f16(float* c, const uint32_t* a, const uint32_t* b) {
    asm volatile(
        "mma.sync.aligned.m16n8k16.row.col.f32.f16.f16.f32 "
        "{%0,%1,%2,%3}, {%4,%5,%6,%7}, {%8,%9}, {%0,%1,%2,%3};"
        : "+f"(c[0]), "+f"(c[1]), "+f"(c[2]), "+f"(c[3])
        : "r"(a[0]), "r"(a[1]), "r"(a[2]), "r"(a[3]), "r"(b[0]), "r"(b[1]));
}

// ---------------------------------------------------------------------------
// Pre-pass A: fp32 -> fp16 RN (x only)
// ---------------------------------------------------------------------------
__global__ void cvt_half_kernel(const float* __restrict__ in, __half* __restrict__ out,
                                size_t n8) {
    size_t i  = (size_t)blockIdx.x * blockDim.x + threadIdx.x;
    size_t st = (size_t)gridDim.x * blockDim.x;
    const float4* pi = (const float4*)in;
    uint4* po = (uint4*)out;
    for (; i < n8; i += st) {
        float4 a = pi[2 * i];
        float4 b = pi[2 * i + 1];
        uint4 v;
        v.x = f22u(a.x, a.y); v.y = f22u(a.z, a.w);
        v.z = f22u(b.x, b.y); v.w = f22u(b.z, b.w);
        po[i] = v;
    }
}

// ---------------------------------------------------------------------------
// Pre-pass B: fp32 [E][K][N] -> fp16 [E][N][K] (transpose + convert)
// ---------------------------------------------------------------------------
__global__ void cvt_transpose_kernel(const float* __restrict__ in, __half* __restrict__ out,
                                     int K, int N) {
    __shared__ float tile[32][33];
    const int e = blockIdx.z;
    const float* src = in  + (size_t)e * K * N;
    __half*      dst = out + (size_t)e * K * N;
    const int n0 = blockIdx.x * 32;
    const int k0 = blockIdx.y * 32;
    const int tx = threadIdx.x, ty = threadIdx.y;
    #pragma unroll
    for (int i = ty; i < 32; i += 8)
        tile[i][tx] = src[(size_t)(k0 + i) * N + (n0 + tx)];
    __syncthreads();
    // 32 n-rows x 16 half2 = 512 half2; 256 threads, 2 each. Vectorized writes.
    #pragma unroll
    for (int idx = ty * 32 + tx; idx < 512; idx += 256) {
        int r  = idx >> 4;     // n row 0..31
        int c2 = idx & 15;     // half2 k-col
        __half2 v = __floats2half2_rn(tile[2 * c2][r], tile[2 * c2 + 1][r]);
        *reinterpret_cast<__half2*>(dst + (size_t)(n0 + r) * K + k0 + 2 * c2) = v;
    }
}

// ---------------------------------------------------------------------------
// Tiling constants (halves). ALL tiles are [rows][BK] with K contiguous.
// ---------------------------------------------------------------------------
#define BK        32     // halves of K per stage (2 x k16 mma steps)
#define STAGES    4
#define TSTRIDE   40     // halves per SMEM tile row (32 + 8 pad): conflict-free ldmatrix
#define T128_B    (128 * TSTRIDE * 2)      // 10240 bytes (128-row tile)
#define T256_B    (256 * TSTRIDE * 2)      // 20480 bytes (256-row tile)
#define FS_STAGE  (3 * T128_B)             // 30720 (A + Bg + Bu)
#define DS_STAGE  (T128_B + T256_B)        // 30720 (A + Bd)

// 128-row tile load: 512 16B-chunks, 2 per thread
__device__ __forceinline__ void load_tile128(uint32_t sdst, const __half* g, size_t ld,
                                             int tid, int maxrow) {
    #pragma unroll
    for (int j = 0; j < 2; ++j) {
        int idx = tid + j * 256;
        int r = idx >> 2, c = idx & 3;
        int gr = (r < maxrow) ? r : 0;
        CP_ASYNC(sdst + (r * TSTRIDE + c * 8) * 2, g + (size_t)gr * ld + c * 8);
    }
}
// 256-row tile load: 1024 chunks, 4 per thread
__device__ __forceinline__ void load_tile256(uint32_t sdst, const __half* g, size_t ld,
                                             int tid) {
    #pragma unroll
    for (int j = 0; j < 4; ++j) {
        int idx = tid + j * 256;
        int r = idx >> 2, c = idx & 3;
        CP_ASYNC(sdst + (r * TSTRIDE + c * 8) * 2, g + (size_t)r * ld + c * 8);
    }
}

// ---------------------------------------------------------------------------
// Fused gate/up GEMM + SwiGLU.  CTA 128x128, 8 warps (wm 0-1, wn 0-3),
// warp tile 64x32 per matrix.  All fragments via ldmatrix.x4.
// ---------------------------------------------------------------------------
__device__ __forceinline__ void compute_stage_fused(
    uint32_t sbase, uint32_t aOff, uint32_t bOff,
    float cg[4][4][4], float cu[4][4][4])
{
    const uint32_t aA = sbase + aOff;
    const uint32_t aG = sbase + T128_B + bOff;
    const uint32_t aU = sbase + 2 * T128_B + bOff;
    #pragma unroll
    for (int ks = 0; ks < 2; ++ks) {
        uint32_t a[4][4];
        #pragma unroll
        for (int mt = 0; mt < 4; ++mt)
            ldm_x4(a[mt][0], a[mt][1], a[mt][2], a[mt][3], aA + ks * 32 + mt * 1280);
        uint32_t bg[4][2], bu[4][2];
        #pragma unroll
        for (int p = 0; p < 2; ++p) {
            ldm_x4(bg[2*p][0], bg[2*p][1], bg[2*p+1][0], bg[2*p+1][1], aG + ks * 32 + p * 1280);
            ldm_x4(bu[2*p][0], bu[2*p][1], bu[2*p+1][0], bu[2*p+1][1], aU + ks * 32 + p * 1280);
        }
        #pragma unroll
        for (int mt = 0; mt < 4; ++mt)
            #pragma unroll
            for (int nt = 0; nt < 4; ++nt) {
                mma_f16(cg[mt][nt], a[mt], bg[nt]);
                mma_f16(cu[mt][nt], a[mt], bu[nt]);
            }
    }
}

__global__ __launch_bounds__(256, 1)
void fused_gate_up(const __half* __restrict__ X, const __half* __restrict__ WG,
                   const __half* __restrict__ WU, __half* __restrict__ OUT,
                   const int* __restrict__ tpe)
{
    const int e = blockIdx.z;
    int start = 0;
    #pragma unroll
    for (int i = 0; i < NEXP; ++i) if (i < e) start += tpe[i];
    const int cnt = tpe[e];
    const int m0 = blockIdx.x * 128;
    if (m0 >= cnt) return;
    const int rows = min(128, cnt - m0);
    const int n0 = blockIdx.y * 128;

    extern __shared__ __half sm[];
    const uint32_t sb = smem_u32(sm);
    const int tid = threadIdx.x, wid = tid >> 5, lane = tid & 31;
    const int wm = wid & 1, wn = wid >> 1;

    const __half* Ag = X  + (size_t)(start + m0) * HID;
    const __half* Gg = WG + (size_t)e * HID * INTER_ + (size_t)n0 * HID;  // [I][H]
    const __half* Ug = WU + (size_t)e * HID * INTER_ + (size_t)n0 * HID;

    // per-lane ldmatrix byte offsets within a tile region
    const uint32_t aOff = ((wm * 64 + (lane & 15)) * TSTRIDE + (lane >> 4) * 8) * 2;
    const uint32_t bOff = ((wn * 32 + ((lane >> 4) & 1) * 8 + (lane & 7)) * TSTRIDE
                           + ((lane >> 3) & 1) * 8) * 2;

    float cg[4][4][4], cu[4][4][4];
    #pragma unroll
    for (int a = 0; a < 4; ++a)
        #pragma unroll
        for (int b = 0; b < 4; ++b)
            #pragma unroll
            for (int c = 0; c < 4; ++c) { cg[a][b][c] = 0.f; cu[a][b][c] = 0.f; }

    const int niter = HID / BK;  // 32
    #pragma unroll
    for (int s = 0; s < STAGES - 1; ++s) {
        const uint32_t st = sb + s * FS_STAGE;
        load_tile128(st,              Ag + s * BK, HID, tid, rows);
        load_tile128(st + T128_B,     Gg + s * BK, HID, tid, 128);
        load_tile128(st + 2 * T128_B, Ug + s * BK, HID, tid, 128);
        CP_COMMIT();
    }
    for (int i = 0; i < niter; ++i) {
        CP_WAIT2();
        __syncthreads();
        compute_stage_fused(sb + (i % STAGES) * FS_STAGE, aOff, bOff, cg, cu);
        const int nb = i + STAGES - 1;
        if (nb < niter) {
            const uint32_t st = sb + (nb % STAGES) * FS_STAGE;
            load_tile128(st,              Ag + nb * BK, HID, tid, rows);
            load_tile128(st + T128_B,     Gg + nb * BK, HID, tid, 128);
            load_tile128(st + 2 * T128_B, Ug + nb * BK, HID, tid, 128);
        }
        CP_COMMIT();
    }

    // Epilogue: SwiGLU, fp16 RN, packed stores
    const int rbase = wm * 64 + (lane >> 2);
    const int cbase = n0 + wn * 32 + 2 * (lane & 3);
    #pragma unroll
    for (int mt = 0; mt < 4; ++mt) {
        #pragma unroll
        for (int nt = 0; nt < 4; ++nt) {
            const int r0 = rbase + mt * 16;
            const int c  = cbase + nt * 8;
            if (r0 < rows) {
                float a0 = cg[mt][nt][0], a1 = cg[mt][nt][1];
                uint32_t v = f22u(a0 / (1.f + __expf(-a0)) * cu[mt][nt][0],
                                  a1 / (1.f + __expf(-a1)) * cu[mt][nt][1]);
                *(uint32_t*)(OUT + (size_t)(start + m0 + r0) * INTER_ + c) = v;
            }
            if (r0 + 8 < rows) {
                float a2 = cg[mt][nt][2], a3 = cg[mt][nt][3];
                uint32_t v = f22u(a2 / (1.f + __expf(-a2)) * cu[mt][nt][2],
                                  a3 / (1.f + __expf(-a3)) * cu[mt][nt][3]);
                *(uint32_t*)(OUT + (size_t)(start + m0 + r0 + 8) * INTER_ + c) = v;
            }
        }
    }
}

// ---------------------------------------------------------------------------
// Down-proj GEMM: out(fp32) = inter @ down^T.  CTA 128x256, warp 64x64.
// ---------------------------------------------------------------------------
__device__ __forceinline__ void compute_stage_down(
    uint32_t sbase, uint32_t aOff, uint32_t bOff, float cc[4][8][4])
{
    const uint32_t aA = sbase + aOff;
    const uint32_t aB = sbase + T128_B + bOff;
    #pragma unroll
    for (int ks = 0; ks < 2; ++ks) {
        uint32_t a[4][4];
        #pragma unroll
        for (int mt = 0; mt < 4; ++mt)
            ldm_x4(a[mt][0], a[mt][1], a[mt][2], a[mt][3], aA + ks * 32 + mt * 1280);
        uint32_t bf[8][2];
        #pragma unroll
        for (int p = 0; p < 4; ++p)
            ldm_x4(bf[2*p][0], bf[2*p][1], bf[2*p+1][0], bf[2*p+1][1], aB + ks * 32 + p * 1280);
        #pragma unroll
        for (int mt = 0; mt < 4; ++mt)
            #pragma unroll
            for (int nt = 0; nt < 8; ++nt)
                mma_f16(cc[mt][nt], a[mt], bf[nt]);
    }
}

__global__ __launch_bounds__(256, 1)
void down_proj(const __half* __restrict__ X, const __half* __restrict__ WD,
               float* __restrict__ OUT, const int* __restrict__ tpe)
{
    const int e = blockIdx.z;
    int start = 0;
    #pragma unroll
    for (int i = 0; i < NEXP; ++i) if (i < e) start += tpe[i];
    const int cnt = tpe[e];
    const int m0 = blockIdx.x * 128;
    if (m0 >= cnt) return;
    const int rows = min(128, cnt - m0);
    const int n0 = blockIdx.y * 256;

    extern __shared__ __half sm[];
    const uint32_t sb = smem_u32(sm);
    const int tid = threadIdx.x, wid = tid >> 5, lane = tid & 31;
    const int wm = wid & 1, wn = wid >> 1;

    const __half* Ag = X  + (size_t)(start + m0) * INTER_;
    const __half* Bg = WD + (size_t)e * HID * INTER_ + (size_t)n0 * INTER_;  // [H][I]

    const uint32_t aOff = ((wm * 64 + (lane & 15)) * TSTRIDE + (lane >> 4) * 8) * 2;
    const uint32_t bOff = ((wn * 64 + ((lane >> 4) & 1) * 8 + (lane & 7)) * TSTRIDE
                           + ((lane >> 3) & 1) * 8) * 2;

    float cc[4][8][4];
    #pragma unroll
    for (int a = 0; a < 4; ++a)
        #pragma unroll
        for (int b = 0; b < 8; ++b)
            #pragma unroll
            for (int c = 0; c < 4; ++c) cc[a][b][c] = 0.f;

    const int niter = INTER_ / BK;  // 88
    #pragma unroll
    for (int s = 0; s < STAGES - 1; ++s) {
        const uint32_t st = sb + s * DS_STAGE;
        load_tile128(st,          Ag + s * BK, INTER_, tid, rows);
        load_tile256(st + T128_B, Bg + s * BK, INTER_, tid);
        CP_COMMIT();
    }
    for (int i = 0; i < niter; ++i) {
        CP_WAIT2();
        __syncthreads();
        compute_stage_down(sb + (i % STAGES) * DS_STAGE, aOff, bOff, cc);
        const int nb = i + STAGES - 1;
        if (nb < niter) {
            const uint32_t st = sb + (nb % STAGES) * DS_STAGE;
            load_tile128(st,          Ag + nb * BK, INTER_, tid, rows);
            load_tile256(st + T128_B, Bg + nb * BK, INTER_, tid);
        }
        CP_COMMIT();
    }

    const int rbase = wm * 64 + (lane >> 2);
    const int cbase = n0 + wn * 64 + 2 * (lane & 3);
    #pragma unroll
    for (int mt = 0; mt < 4; ++mt) {
        #pragma unroll
        for (int nt = 0; nt < 8; ++nt) {
            const int r0 = rbase + mt * 16;
            const int c  = cbase + nt * 8;
            if (r0 < rows) {
                float2 v = make_float2(cc[mt][nt][0], cc[mt][nt][1]);
                *reinterpret_cast<float2*>(OUT + (size_t)(start + m0 + r0) * HID + c) = v;
            }
            if (r0 + 8 < rows) {
                float2 v = make_float2(cc[mt][nt][2], cc[mt][nt][3]);
                *reinterpret_cast<float2*>(OUT + (size_t)(start + m0 + r0 + 8) * HID + c) = v;
            }
        }
    }
}

// ---------------------------------------------------------------------------
// Host side
// ---------------------------------------------------------------------------
extern "C" void kernel_launch(void* const* d_in, const int* in_sizes, int n_in,
                              void* d_out, int out_size)
{
    const float* x    = (const float*)d_in[0];   // [T, H]
    const float* gate = (const float*)d_in[1];   // [E, H, I]
    const float* up   = (const float*)d_in[2];   // [E, H, I]
    const float* down = (const float*)d_in[3];   // [E, I, H]
    const int*   tpe  = (const int*)d_in[4];     // [E]
    float* out = (float*)d_out;                  // [T, H]

    const int T = in_sizes[0] / HID;

    __half *xh, *wg, *wu, *wd, *inter;
    cudaGetSymbolAddress((void**)&xh, g_xh);
    cudaGetSymbolAddress((void**)&wg, g_wg);
    cudaGetSymbolAddress((void**)&wu, g_wu);
    cudaGetSymbolAddress((void**)&wd, g_wd);
    cudaGetSymbolAddress((void**)&inter, g_inter);

    // Pre-pass: convert x; transpose+convert weights to [E][N][K] fp16
    cvt_half_kernel<<<1024, 256>>>(x, xh, (size_t)T * HID / 8);
    dim3 tb(32, 8);
    cvt_transpose_kernel<<<dim3(INTER_ / 32, HID / 32, NEXP), tb>>>(gate, wg, HID, INTER_);
    cvt_transpose_kernel<<<dim3(INTER_ / 32, HID / 32, NEXP), tb>>>(up,   wu, HID, INTER_);
    cvt_transpose_kernel<<<dim3(HID / 32, INTER_ / 32, NEXP), tb>>>(down, wd, INTER_, HID);

    cudaFuncSetAttribute(fused_gate_up, cudaFuncAttributeMaxDynamicSharedMemorySize,
                         STAGES * FS_STAGE);
    cudaFuncSetAttribute(down_proj, cudaFuncAttributeMaxDynamicSharedMemorySize,
                         STAGES * DS_STAGE);

    const int mtiles = (T + 127) / 128;

    dim3 g1(mtiles, INTER_ / 128, NEXP);
    fused_gate_up<<<g1, 256, STAGES * FS_STAGE>>>(xh, wg, wu, inter, tpe);

    dim3 g2(mtiles, HID / 256, NEXP);
    down_proj<<<g2, 256, STAGES * DS_STAGE>>>(inter, wd, out, tpe);
}

// round 9
// speedup vs baseline: 8.2357x; 1.1683x over previous
#include <cuda_runtime.h>
#include <cuda.h>
#include <cuda_fp16.h>
#include <cstdint>
#include <cstddef>

#define HID    1024
#define INTER_ 2816
#define MAX_T  8192
#define NEXP   8

// ---------------------------------------------------------------------------
// Scratch (static device globals; allocation-free rule)
// Weights kept in NATIVE layout [E][K][N], just converted to fp16.
// ---------------------------------------------------------------------------
__device__ __align__(128) __half g_xh[(size_t)MAX_T * HID];          // x fp16 [T][H]
__device__ __align__(128) __half g_wg[(size_t)NEXP * HID * INTER_];  // gate fp16 [E][H][I]
__device__ __align__(128) __half g_wu[(size_t)NEXP * HID * INTER_];  // up fp16   [E][H][I]
__device__ __align__(128) __half g_wd[(size_t)NEXP * HID * INTER_];  // down fp16 [E][I][H]
__device__ __align__(128) __half g_inter[(size_t)MAX_T * INTER_];    // [T][I]

// ---------------------------------------------------------------------------
// Helpers
// ---------------------------------------------------------------------------
__device__ __forceinline__ uint32_t smem_u32(const void* p) {
    uint32_t a;
    asm("{ .reg .u64 t; cvta.to.shared.u64 t, %1; cvt.u32.u64 %0, t; }" : "=r"(a) : "l"(p));
    return a;
}

__device__ __forceinline__ uint32_t f22u(float a, float b) {
    __half2 h = __floats2half2_rn(a, b);
    return *reinterpret_cast<uint32_t*>(&h);
}

#define CP_ASYNC(sm, gm) \
    asm volatile("cp.async.cg.shared.global [%0], [%1], 16;" :: "r"(sm), "l"(gm))
#define CP_COMMIT() asm volatile("cp.async.commit_group;" ::: "memory")
#define CP_WAIT2()  asm volatile("cp.async.wait_group 2;" ::: "memory")

__device__ __forceinline__ void ldm_x4(uint32_t& r0, uint32_t& r1, uint32_t& r2,
                                       uint32_t& r3, uint32_t addr) {
    asm volatile("ldmatrix.sync.aligned.m8n8.x4.shared.b16 {%0,%1,%2,%3}, [%4];"
                 : "=r"(r0), "=r"(r1), "=r"(r2), "=r"(r3) : "r"(addr));
}
__device__ __forceinline__ void ldm_x4_trans(uint32_t& r0, uint32_t& r1, uint32_t& r2,
                                             uint32_t& r3, uint32_t addr) {
    asm volatile("ldmatrix.sync.aligned.m8n8.x4.trans.shared.b16 {%0,%1,%2,%3}, [%4];"
                 : "=r"(r0), "=r"(r1), "=r"(r2), "=r"(r3) : "r"(addr));
}

// m16n8k16 fp16 MMA, fp32 accum
__device__ __forceinline__ void mma_f16(float* c, const uint32_t* a, const uint32_t* b) {
    asm volatile(
        "mma.sync.aligned.m16n8k16.row.col.f32.f16.f16.f32 "
        "{%0,%1,%2,%3}, {%4,%5,%6,%7}, {%8,%9}, {%0,%1,%2,%3};"
        : "+f"(c[0]), "+f"(c[1]), "+f"(c[2]), "+f"(c[3])
        : "r"(a[0]), "r"(a[1]), "r"(a[2]), "r"(a[3]), "r"(b[0]), "r"(b[1]));
}

// ---------------------------------------------------------------------------
// Pre-pass: fp32 -> fp16 RN convert (16 floats per thread-iter)
// ---------------------------------------------------------------------------
__global__ void cvt_half_kernel(const float* __restrict__ in, __half* __restrict__ out,
                                size_t n8) {
    size_t i  = (size_t)blockIdx.x * blockDim.x + threadIdx.x;
    size_t st = (size_t)gridDim.x * blockDim.x;
    const float4* pi = (const float4*)in;
    uint4* po = (uint4*)out;
    for (; i < n8; i += st) {
        float4 a = pi[2 * i];
        float4 b = pi[2 * i + 1];
        uint4 v;
        v.x = f22u(a.x, a.y); v.y = f22u(a.z, a.w);
        v.z = f22u(b.x, b.y); v.w = f22u(b.z, b.w);
        po[i] = v;
    }
}

// ---------------------------------------------------------------------------
// Tiling constants (halves).
// A tiles: [128 m-rows][BK], K contiguous, stride 40.
// B tiles: [BK k-rows][BN], N contiguous, stride BN+8 (272/528 B: row shift
//          = 4 banks, so 8-row ldmatrix phases are conflict-free).
// ---------------------------------------------------------------------------
#define BK        32
#define STAGES    4
#define ASTRIDE   40     // halves (32 + 8 pad)
#define BSTR_F    136    // fused B: 128 + 8
#define BSTR_D    264    // down B: 256 + 8
#define TA_BYTES  (128 * ASTRIDE * 2)      // 10240
#define BF_BYTES  (BK * BSTR_F * 2)        // 8704
#define BD_BYTES  (BK * BSTR_D * 2)        // 16896
#define FS_STAGE  (TA_BYTES + 2 * BF_BYTES)  // 27648
#define DS_STAGE  (TA_BYTES + BD_BYTES)      // 27136

// A tile load: 128 x 32 halves, 512 16B-chunks, 2 per thread
__device__ __forceinline__ void load_tileA(uint32_t sdst, const __half* g, size_t ld,
                                           int tid, int maxrow) {
    #pragma unroll
    for (int j = 0; j < 2; ++j) {
        int idx = tid + j * 256;
        int r = idx >> 2, c = idx & 3;
        int gr = (r < maxrow) ? r : 0;
        CP_ASYNC(sdst + (r * ASTRIDE + c * 8) * 2, g + (size_t)gr * ld + c * 8);
    }
}
// Fused B tile: 32 k-rows x 128 n, 512 chunks
__device__ __forceinline__ void load_tileBF(uint32_t sdst, const __half* g, size_t ld,
                                            int tid) {
    #pragma unroll
    for (int j = 0; j < 2; ++j) {
        int idx = tid + j * 256;
        int r = idx >> 4, c = idx & 15;
        CP_ASYNC(sdst + (r * BSTR_F + c * 8) * 2, g + (size_t)r * ld + c * 8);
    }
}
// Down B tile: 32 k-rows x 256 n, 1024 chunks
__device__ __forceinline__ void load_tileBD(uint32_t sdst, const __half* g, size_t ld,
                                            int tid) {
    #pragma unroll
    for (int j = 0; j < 4; ++j) {
        int idx = tid + j * 256;
        int r = idx >> 5, c = idx & 31;
        CP_ASYNC(sdst + (r * BSTR_D + c * 8) * 2, g + (size_t)r * ld + c * 8);
    }
}

// ---------------------------------------------------------------------------
// Fused gate/up GEMM + SwiGLU.  CTA 128x128, 8 warps (wm 0-1, wn 0-3),
// warp tile 64x32 per matrix.  A: ldmatrix; B: ldmatrix.trans on [K][N].
// ---------------------------------------------------------------------------
__device__ __forceinline__ void compute_stage_fused(
    uint32_t sbase, uint32_t aOff, uint32_t bOff,
    float cg[4][4][4], float cu[4][4][4])
{
    const uint32_t aA = sbase + aOff;
    const uint32_t aG = sbase + TA_BYTES + bOff;
    const uint32_t aU = aG + BF_BYTES;
    #pragma unroll
    for (int ks = 0; ks < 2; ++ks) {
        uint32_t a[4][4];
        #pragma unroll
        for (int mt = 0; mt < 4; ++mt)
            ldm_x4(a[mt][0], a[mt][1], a[mt][2], a[mt][3], aA + ks * 32 + mt * 1280);
        uint32_t bg[4][2], bu[4][2];
        const uint32_t ksb = ks * 16 * BSTR_F * 2;
        #pragma unroll
        for (int p = 0; p < 2; ++p) {
            ldm_x4_trans(bg[2*p][0], bg[2*p][1], bg[2*p+1][0], bg[2*p+1][1],
                         aG + ksb + p * 32);
            ldm_x4_trans(bu[2*p][0], bu[2*p][1], bu[2*p+1][0], bu[2*p+1][1],
                         aU + ksb + p * 32);
        }
        #pragma unroll
        for (int mt = 0; mt < 4; ++mt)
            #pragma unroll
            for (int nt = 0; nt < 4; ++nt) {
                mma_f16(cg[mt][nt], a[mt], bg[nt]);
                mma_f16(cu[mt][nt], a[mt], bu[nt]);
            }
    }
}

__global__ __launch_bounds__(256, 1)
void fused_gate_up(const __half* __restrict__ X, const __half* __restrict__ WG,
                   const __half* __restrict__ WU, __half* __restrict__ OUT,
                   const int* __restrict__ tpe)
{
    const int e = blockIdx.z;
    int start = 0;
    #pragma unroll
    for (int i = 0; i < NEXP; ++i) if (i < e) start += tpe[i];
    const int cnt = tpe[e];
    const int m0 = blockIdx.x * 128;
    if (m0 >= cnt) return;
    const int rows = min(128, cnt - m0);
    const int n0 = blockIdx.y * 128;

    extern __shared__ __half sm[];
    const uint32_t sb = smem_u32(sm);
    const int tid = threadIdx.x, wid = tid >> 5, lane = tid & 31;
    const int wm = wid & 1, wn = wid >> 1;

    const __half* Ag = X  + (size_t)(start + m0) * HID;
    const __half* Gg = WG + (size_t)e * HID * INTER_ + n0;   // [K=H][N=I]
    const __half* Ug = WU + (size_t)e * HID * INTER_ + n0;

    // A fragment base (non-trans x4): lanes 0-15 -> m rows, lanes 16-31 -> k+8
    const uint32_t aOff = ((wm * 64 + (lane & 15)) * ASTRIDE + (lane >> 4) * 8) * 2;
    // B fragment base (.trans x4 on [K][N]): q=lane>>3 -> (kb, n8) = (q&1, q>>1)
    const uint32_t bRow = ((lane >> 3) & 1) * 8 + (lane & 7);
    const uint32_t bOff = (bRow * BSTR_F + wn * 32 + (lane >> 4) * 8) * 2;

    float cg[4][4][4], cu[4][4][4];
    #pragma unroll
    for (int a = 0; a < 4; ++a)
        #pragma unroll
        for (int b = 0; b < 4; ++b)
            #pragma unroll
            for (int c = 0; c < 4; ++c) { cg[a][b][c] = 0.f; cu[a][b][c] = 0.f; }

    const int niter = HID / BK;  // 32
    #pragma unroll
    for (int s = 0; s < STAGES - 1; ++s) {
        const uint32_t st = sb + s * FS_STAGE;
        load_tileA (st,                       Ag + s * BK, HID, tid, rows);
        load_tileBF(st + TA_BYTES,            Gg + (size_t)s * BK * INTER_, INTER_, tid);
        load_tileBF(st + TA_BYTES + BF_BYTES, Ug + (size_t)s * BK * INTER_, INTER_, tid);
        CP_COMMIT();
    }
    for (int i = 0; i < niter; ++i) {
        CP_WAIT2();
        __syncthreads();
        compute_stage_fused(sb + (i % STAGES) * FS_STAGE, aOff, bOff, cg, cu);
        const int nb = i + STAGES - 1;
        if (nb < niter) {
            const uint32_t st = sb + (nb % STAGES) * FS_STAGE;
            load_tileA (st,                       Ag + nb * BK, HID, tid, rows);
            load_tileBF(st + TA_BYTES,            Gg + (size_t)nb * BK * INTER_, INTER_, tid);
            load_tileBF(st + TA_BYTES + BF_BYTES, Ug + (size_t)nb * BK * INTER_, INTER_, tid);
        }
        CP_COMMIT();
    }

    // Epilogue: SwiGLU, fp16 RN, packed stores
    const int rbase = wm * 64 + (lane >> 2);
    const int cbase = n0 + wn * 32 + 2 * (lane & 3);
    #pragma unroll
    for (int mt = 0; mt < 4; ++mt) {
        #pragma unroll
        for (int nt = 0; nt < 4; ++nt) {
            const int r0 = rbase + mt * 16;
            const int c  = cbase + nt * 8;
            if (r0 < rows) {
                float a0 = cg[mt][nt][0], a1 = cg[mt][nt][1];
                uint32_t v = f22u(a0 / (1.f + __expf(-a0)) * cu[mt][nt][0],
                                  a1 / (1.f + __expf(-a1)) * cu[mt][nt][1]);
                *(uint32_t*)(OUT + (size_t)(start + m0 + r0) * INTER_ + c) = v;
            }
            if (r0 + 8 < rows) {
                float a2 = cg[mt][nt][2], a3 = cg[mt][nt][3];
                uint32_t v = f22u(a2 / (1.f + __expf(-a2)) * cu[mt][nt][2],
                                  a3 / (1.f + __expf(-a3)) * cu[mt][nt][3]);
                *(uint32_t*)(OUT + (size_t)(start + m0 + r0 + 8) * INTER_ + c) = v;
            }
        }
    }
}

// ---------------------------------------------------------------------------
// Down-proj GEMM: out(fp32) = inter @ down.  CTA 128x256, warp 64x64.
// ---------------------------------------------------------------------------
__device__ __forceinline__ void compute_stage_down(
    uint32_t sbase, uint32_t aOff, uint32_t bOff, float cc[4][8][4])
{
    const uint32_t aA = sbase + aOff;
    const uint32_t aB = sbase + TA_BYTES + bOff;
    #pragma unroll
    for (int ks = 0; ks < 2; ++ks) {
        uint32_t a[4][4];
        #pragma unroll
        for (int mt = 0; mt < 4; ++mt)
            ldm_x4(a[mt][0], a[mt][1], a[mt][2], a[mt][3], aA + ks * 32 + mt * 1280);
        uint32_t bf[8][2];
        const uint32_t ksb = ks * 16 * BSTR_D * 2;
        #pragma unroll
        for (int p = 0; p < 4; ++p)
            ldm_x4_trans(bf[2*p][0], bf[2*p][1], bf[2*p+1][0], bf[2*p+1][1],
                         aB + ksb + p * 32);
        #pragma unroll
        for (int mt = 0; mt < 4; ++mt)
            #pragma unroll
            for (int nt = 0; nt < 8; ++nt)
                mma_f16(cc[mt][nt], a[mt], bf[nt]);
    }
}

__global__ __launch_bounds__(256, 1)
void down_proj(const __half* __restrict__ X, const __half* __restrict__ WD,
               float* __restrict__ OUT, const int* __restrict__ tpe)
{
    const int e = blockIdx.z;
    int start = 0;
    #pragma unroll
    for (int i = 0; i < NEXP; ++i) if (i < e) start += tpe[i];
    const int cnt = tpe[e];
    const int m0 = blockIdx.x * 128;
    if (m0 >= cnt) return;
    const int rows = min(128, cnt - m0);
    const int n0 = blockIdx.y * 256;

    extern __shared__ __half sm[];
    const uint32_t sb = smem_u32(sm);
    const int tid = threadIdx.x, wid = tid >> 5, lane = tid & 31;
    const int wm = wid & 1, wn = wid >> 1;

    const __half* Ag = X  + (size_t)(start + m0) * INTER_;
    const __half* Bg = WD + (size_t)e * HID * INTER_ + n0;   // [K=I][N=H]

    const uint32_t aOff = ((wm * 64 + (lane & 15)) * ASTRIDE + (lane >> 4) * 8) * 2;
    const uint32_t bRow = ((lane >> 3) & 1) * 8 + (lane & 7);
    const uint32_t bOff = (bRow * BSTR_D + wn * 64 + (lane >> 4) * 8) * 2;

    float cc[4][8][4];
    #pragma unroll
    for (int a = 0; a < 4; ++a)
        #pragma unroll
        for (int b = 0; b < 8; ++b)
            #pragma unroll
            for (int c = 0; c < 4; ++c) cc[a][b][c] = 0.f;

    const int niter = INTER_ / BK;  // 88
    #pragma unroll
    for (int s = 0; s < STAGES - 1; ++s) {
        const uint32_t st = sb + s * DS_STAGE;
        load_tileA (st,            Ag + s * BK, INTER_, tid, rows);
        load_tileBD(st + TA_BYTES, Bg + (size_t)s * BK * HID, HID, tid);
        CP_COMMIT();
    }
    for (int i = 0; i < niter; ++i) {
        CP_WAIT2();
        __syncthreads();
        compute_stage_down(sb + (i % STAGES) * DS_STAGE, aOff, bOff, cc);
        const int nb = i + STAGES - 1;
        if (nb < niter) {
            const uint32_t st = sb + (nb % STAGES) * DS_STAGE;
            load_tileA (st,            Ag + nb * BK, INTER_, tid, rows);
            load_tileBD(st + TA_BYTES, Bg + (size_t)nb * BK * HID, HID, tid);
        }
        CP_COMMIT();
    }

    const int rbase = wm * 64 + (lane >> 2);
    const int cbase = n0 + wn * 64 + 2 * (lane & 3);
    #pragma unroll
    for (int mt = 0; mt < 4; ++mt) {
        #pragma unroll
        for (int nt = 0; nt < 8; ++nt) {
            const int r0 = rbase + mt * 16;
            const int c  = cbase + nt * 8;
            if (r0 < rows) {
                float2 v = make_float2(cc[mt][nt][0], cc[mt][nt][1]);
                *reinterpret_cast<float2*>(OUT + (size_t)(start + m0 + r0) * HID + c) = v;
            }
            if (r0 + 8 < rows) {
                float2 v = make_float2(cc[mt][nt][2], cc[mt][nt][3]);
                *reinterpret_cast<float2*>(OUT + (size_t)(start + m0 + r0 + 8) * HID + c) = v;
            }
        }
    }
}

// ---------------------------------------------------------------------------
// Host side
// ---------------------------------------------------------------------------
extern "C" void kernel_launch(void* const* d_in, const int* in_sizes, int n_in,
                              void* d_out, int out_size)
{
    const float* x    = (const float*)d_in[0];   // [T, H]
    const float* gate = (const float*)d_in[1];   // [E, H, I]
    const float* up   = (const float*)d_in[2];   // [E, H, I]
    const float* down = (const float*)d_in[3];   // [E, I, H]
    const int*   tpe  = (const int*)d_in[4];     // [E]
    float* out = (float*)d_out;                  // [T, H]

    const int T = in_sizes[0] / HID;
    const size_t wsz = (size_t)NEXP * HID * INTER_;

    __half *xh, *wg, *wu, *wd, *inter;
    cudaGetSymbolAddress((void**)&xh, g_xh);
    cudaGetSymbolAddress((void**)&wg, g_wg);
    cudaGetSymbolAddress((void**)&wu, g_wu);
    cudaGetSymbolAddress((void**)&wd, g_wd);
    cudaGetSymbolAddress((void**)&inter, g_inter);

    // Pre-pass: fp32 -> fp16 RN converts only (no transpose)
    cvt_half_kernel<<<1024, 256>>>(x,    xh, (size_t)T * HID / 8);
    cvt_half_kernel<<<4096, 256>>>(gate, wg, wsz / 8);
    cvt_half_kernel<<<4096, 256>>>(up,   wu, wsz / 8);
    cvt_half_kernel<<<4096, 256>>>(down, wd, wsz / 8);

    cudaFuncSetAttribute(fused_gate_up, cudaFuncAttributeMaxDynamicSharedMemorySize,
                         STAGES * FS_STAGE);
    cudaFuncSetAttribute(down_proj, cudaFuncAttributeMaxDynamicSharedMemorySize,
                         STAGES * DS_STAGE);

    const int mtiles = (T + 127) / 128;

    dim3 g1(mtiles, INTER_ / 128, NEXP);
    fused_gate_up<<<g1, 256, STAGES * FS_STAGE>>>(xh, wg, wu, inter, tpe);

    dim3 g2(mtiles, HID / 256, NEXP);
    down_proj<<<g2, 256, STAGES * DS_STAGE>>>(inter, wd, out, tpe);
}